// round 17
// baseline (speedup 1.0000x reference)
#include <cuda_runtime.h>
#include <cuda_bf16.h>
#include <math.h>
#include <float.h>
#include <stdint.h>

#define WAY 5
#define SHOT 5
#define QUERY 15
#define EMB 640
#define NMEM 100000
#define NSIM (SHOT + NMEM)   // 100005 candidates per way
#define TOPK 8
#define EPS 1e-12f
#define INV_TEMP (1.0f / 64.0f)

#define ROWS 4               // rows per warp in k2
#define SPLITS 32            // scan splits per way in k3
#define CHUNK ((NSIM + SPLITS - 1) / SPLITS)   // 3126
#define NBLK (WAY * SPLITS)  // 160

// ---------------- device scratch (static, allocation-free) ----------------
__device__ __align__(16) float g_c[WAY][EMB];   // per-way centroids
__device__ float g_sim[WAY][NSIM];              // similarity vector per way
__device__ unsigned long long g_pk[WAY][SPLITS][TOPK];  // packed partial top-k keys
__device__ unsigned g_done;                     // completion counter (self-resetting)

typedef unsigned long long ull;

__device__ __forceinline__ float warp_sum(float v) {
#pragma unroll
    for (int o = 16; o; o >>= 1) v += __shfl_xor_sync(0xffffffffu, v, o);
    return v;
}

// orderable-uint transform: key order == float order
__device__ __forceinline__ unsigned ford(float f) {
    unsigned u = __float_as_uint(f);
    return (u & 0x80000000u) ? ~u : (u | 0x80000000u);
}
__device__ __forceinline__ unsigned unford(unsigned u) {
    return (u & 0x80000000u) ? (u & 0x7fffffffu) : ~u;
}
__device__ __forceinline__ ull warp_max_u64(ull m) {
#pragma unroll
    for (int o = 16; o; o >>= 1) {
        ull t = __shfl_xor_sync(0xffffffffu, m, o);
        if (t > m) m = t;
    }
    return m;
}

// ---------------- kernel 1: per-way support prep (grid = WAY) ---------------
__global__ void k1_support(const float* __restrict__ inst) {
    int w = blockIdx.x;
    int wid  = threadIdx.x >> 5;
    int lane = threadIdx.x & 31;

    __shared__ float sinv[SHOT];
    __shared__ float sc[EMB];

    if (wid < SHOT) {
        const float* row = inst + (size_t)(wid * WAY + w) * EMB;
        float ss = 0.f;
#pragma unroll
        for (int i = 0; i < 20; i++) {
            float v = row[lane + 32 * i];
            ss += v * v;
        }
        ss = warp_sum(ss);
        if (lane == 0) sinv[wid] = 1.0f / fmaxf(sqrtf(ss), EPS);
    }
    __syncthreads();

    for (int d = threadIdx.x; d < EMB; d += blockDim.x) {
        float s = 0.f;
#pragma unroll
        for (int t = 0; t < SHOT; t++)
            s += inst[(size_t)(t * WAY + w) * EMB + d] * sinv[t];
        s *= (1.0f / SHOT);
        sc[d] = s;
        g_c[w][d] = s;
    }
    __syncthreads();

    if (wid < SHOT) {
        const float* row = inst + (size_t)(wid * WAY + w) * EMB;
        float dot = 0.f;
#pragma unroll
        for (int i = 0; i < 20; i++) {
            int d = lane + 32 * i;
            dot += row[d] * sc[d];
        }
        dot = warp_sum(dot);
        if (lane == 0) g_sim[w][wid] = dot * sinv[wid];
    }
}

// ---------------- kernel 2: memory-bank scan (R15 proven body, 62us) --------
__global__ void __launch_bounds__(256, 4) k2_memscan(const float* __restrict__ mem) {
    __shared__ float4 sc[WAY][EMB / 4];   // centroids, 12.8 KB
    for (int i = threadIdx.x; i < WAY * EMB / 4; i += blockDim.x)
        (&sc[0][0])[i] = ((const float4*)g_c)[i];
    __syncthreads();

    int wg   = (blockIdx.x * blockDim.x + threadIdx.x) >> 5;
    int lane = threadIdx.x & 31;
    int row0 = wg * ROWS;
    if (row0 >= NMEM) return;

    const float4* base = (const float4*)(mem + (size_t)row0 * EMB);  // row stride 160

    float acc[ROWS][WAY];
    float ssq[ROWS];
#pragma unroll
    for (int r = 0; r < ROWS; r++) {
        ssq[r] = 0.f;
#pragma unroll
        for (int w = 0; w < WAY; w++) acc[r][w] = 0.f;
    }

#pragma unroll
    for (int i = 0; i < 5; i++) {
        int ci = lane + 32 * i;
        float4 v[ROWS];
#pragma unroll
        for (int r = 0; r < ROWS; r++) v[r] = __ldg(base + (size_t)r * 160 + ci);

#pragma unroll
        for (int r = 0; r < ROWS; r++)
            ssq[r] += v[r].x * v[r].x + v[r].y * v[r].y
                    + v[r].z * v[r].z + v[r].w * v[r].w;

#pragma unroll
        for (int w = 0; w < WAY; w++) {
            float4 c = sc[w][ci];
#pragma unroll
            for (int r = 0; r < ROWS; r++)
                acc[r][w] += v[r].x * c.x + v[r].y * c.y
                           + v[r].z * c.z + v[r].w * c.w;
        }
    }

#pragma unroll
    for (int r = 0; r < ROWS; r++) {
        ssq[r] = warp_sum(ssq[r]);
#pragma unroll
        for (int w = 0; w < WAY; w++) {
#pragma unroll
            for (int o = 16; o; o >>= 1)
                acc[r][w] += __shfl_xor_sync(0xffffffffu, acc[r][w], o);
        }
        float inv = 1.0f / fmaxf(sqrtf(ssq[r]), EPS);
        if (lane < WAY) {
            float a = (lane == 0) ? acc[r][0] :
                      (lane == 1) ? acc[r][1] :
                      (lane == 2) ? acc[r][2] :
                      (lane == 3) ? acc[r][3] : acc[r][4];
            g_sim[lane][SHOT + row0 + r] = a * inv;
        }
    }
}

// ---------------- register-resident insert (static indices only) ------------
__device__ __forceinline__ void insert8(float* bv, int* bi, float v, int i) {
    if (v > bv[TOPK - 1]) {
        float cv = v; int ci = i;
#pragma unroll
        for (int j = 0; j < TOPK; j++) {
            if (cv > bv[j]) {
                float tv = bv[j]; bv[j] = cv; cv = tv;
                int   ti = bi[j]; bi[j] = ci; ci = ti;
            }
        }
    }
}

// ---------------- kernel 3: fused top-k + merge + proto + logits ------------
// 160 blocks x 256 threads. Phase A: per-split top-8 -> packed u64 keys.
// Phase B (last block): per-way selection, prototypes, norms, logits.
#define K3_THREADS 256
__global__ void k3_fused(const float* __restrict__ inst,
                         const float* __restrict__ mem,
                         float* __restrict__ out) {
    int w = blockIdx.x / SPLITS;
    int s = blockIdx.x % SPLITS;
    int lo = s * CHUNK;
    int hi = min(lo + CHUNK, NSIM);
    const float* sim = g_sim[w];
    int tid = threadIdx.x;
    int lane = tid & 31, wid = tid >> 5;

    // ---------- Phase A: partial top-8 for (way w, split s) ----------
    float bv[TOPK]; int bi[TOPK];
#pragma unroll
    for (int j = 0; j < TOPK; j++) { bv[j] = -FLT_MAX; bi[j] = 0x7fffffff; }

    int i = lo + tid;
    for (; i + 3 * K3_THREADS < hi; i += 4 * K3_THREADS) {
        float v0 = sim[i];
        float v1 = sim[i + K3_THREADS];
        float v2 = sim[i + 2 * K3_THREADS];
        float v3 = sim[i + 3 * K3_THREADS];
        insert8(bv, bi, v0, i);
        insert8(bv, bi, v1, i + K3_THREADS);
        insert8(bv, bi, v2, i + 2 * K3_THREADS);
        insert8(bv, bi, v3, i + 3 * K3_THREADS);
    }
    for (; i < hi; i += K3_THREADS) insert8(bv, bi, sim[i], i);

    ull k[TOPK];
#pragma unroll
    for (int j = 0; j < TOPK; j++)
        k[j] = ((ull)ford(bv[j]) << 32) | (unsigned)(0x7fffffff - bi[j]);

    __shared__ ull swarp[K3_THREADS / 32][TOPK];   // 8 warps x 8 keys
#pragma unroll
    for (int j = 0; j < TOPK; j++) {
        ull loc = k[0];
#pragma unroll
        for (int t = 1; t < TOPK; t++) loc = (k[t] > loc) ? k[t] : loc;
        ull m = warp_max_u64(loc);
#pragma unroll
        for (int t = 0; t < TOPK; t++)
            if (k[t] == m) k[t] = 0ull;
        if (lane == 0) swarp[wid][j] = m;
    }
    __syncthreads();

    if (wid == 0) {
        ull a = (&swarp[0][0])[lane];
        ull b = (&swarp[0][0])[lane + 32];
#pragma unroll
        for (int j = 0; j < TOPK; j++) {
            ull loc = (a > b) ? a : b;
            ull m = warp_max_u64(loc);
            if (a == m) a = 0ull;
            if (b == m) b = 0ull;
            if (lane == 0) g_pk[w][s][j] = m;
        }
    }

    // ---------- completion count ----------
    __threadfence();
    __syncthreads();
    __shared__ unsigned slast;
    if (tid == 0) slast = atomicAdd(&g_done, 1u);
    __syncthreads();
    if (slast != NBLK - 1) return;
    if (tid == 0) g_done = 0;          // reset for next graph replay
    __threadfence();

    // ---------- Phase B (last block): merge + proto + logits ----------
    __shared__ ull  sld[WAY * SPLITS * TOPK];   // 1280 keys, 10 KB
    __shared__ float svals[WAY][TOPK];
    __shared__ int   sidx[WAY][TOPK];
    __shared__ float sp[WAY][EMB];              // 12.8 KB
    __shared__ float red[8];
    __shared__ float sinv[WAY];

    for (int t = tid; t < WAY * SPLITS * TOPK; t += K3_THREADS)
        sld[t] = (&g_pk[0][0][0])[t];
    __syncthreads();

    // warp w (w < WAY): top-8 of its 256 keys (8 per lane)
    if (wid < WAY) {
        ull kk[8];
#pragma unroll
        for (int t = 0; t < 8; t++)
            kk[t] = sld[wid * (SPLITS * TOPK) + lane + 32 * t];
#pragma unroll
        for (int j = 0; j < TOPK; j++) {
            ull loc = kk[0];
#pragma unroll
            for (int t = 1; t < 8; t++) loc = (kk[t] > loc) ? kk[t] : loc;
            ull m = warp_max_u64(loc);
#pragma unroll
            for (int t = 0; t < 8; t++)
                if (kk[t] == m) kk[t] = 0ull;
            if (lane == 0) {
                svals[wid][j] = __uint_as_float(unford((unsigned)(m >> 32)));
                sidx[wid][j]  = 0x7fffffff - (int)(unsigned)(m & 0xffffffffu);
            }
        }
    }
    __syncthreads();

    // prototypes (keep /denom for reference parity)
    for (int it = tid; it < WAY * EMB; it += K3_THREADS) {
        int w2 = it / EMB, d = it % EMB;
        float denom = 0.f, numer = 0.f;
#pragma unroll
        for (int j = 0; j < TOPK; j++) {
            float v = svals[w2][j];
            int idx = sidx[w2][j];
            const float* src = (idx < SHOT)
                ? inst + (size_t)(idx * WAY + w2) * EMB
                : mem + (size_t)(idx - SHOT) * EMB;
            denom += v;
            numer += v * src[d];
        }
        sp[w2][d] = numer / denom;
    }
    __syncthreads();

    // per-way norms (deterministic)
    for (int w2 = 0; w2 < WAY; w2++) {
        float part = 0.f;
        for (int d = tid; d < EMB; d += K3_THREADS) {
            float p = sp[w2][d];
            part += p * p;
        }
        part = warp_sum(part);
        if (lane == 0) red[wid] = part;
        __syncthreads();
        if (tid == 0) {
            float t = 0.f;
#pragma unroll
            for (int u = 0; u < 8; u++) t += red[u];
            sinv[w2] = INV_TEMP / fmaxf(sqrtf(t), EPS);
        }
        __syncthreads();
    }

    // logits: 8 warps, warp u handles queries u, u+8, ...
    for (int q = wid; q < QUERY * WAY; q += K3_THREADS / 32) {
        const float* qr = inst + (size_t)(SHOT * WAY + q) * EMB;
        float qv[20];
#pragma unroll
        for (int u = 0; u < 20; u++) qv[u] = qr[lane + 32 * u];
#pragma unroll
        for (int w2 = 0; w2 < WAY; w2++) {
            float dot = 0.f;
#pragma unroll
            for (int u = 0; u < 20; u++) dot += qv[u] * sp[w2][lane + 32 * u];
            dot = warp_sum(dot);
            if (lane == 0) out[q * WAY + w2] = dot * sinv[w2];
        }
    }
}

// ---------------- launch ----------------------------------------------------
extern "C" void kernel_launch(void* const* d_in, const int* in_sizes, int n_in,
                              void* d_out, int out_size) {
    const float* inst = (const float*)d_in[0];   // [100, 640] fp32
    const float* mem  = (const float*)d_in[1];   // [100000, 640] fp32
    float* out = (float*)d_out;                  // [75, 5] fp32

    k1_support<<<WAY, 256>>>(inst);

    int warps  = (NMEM + ROWS - 1) / ROWS;       // 25000
    int blocks = (warps + 7) / 8;                // 3125
    k2_memscan<<<blocks, 256>>>(mem);

    k3_fused<<<NBLK, K3_THREADS>>>(inst, mem, out);
}